// round 13
// baseline (speedup 1.0000x reference)
#include <cuda_runtime.h>
#include <cuda_fp16.h>
#include <cstdint>

#define IN_F   4096
#define OUT_F  11008
#define NG     704512          // IN_F*OUT_F/64
#define MROWS  8192            // 4*2048

#define BM 128
#define BN 128
#define BK 32
#define NKB (IN_F / BK)        // 128
#define STAGES 4
#define A_STG_BYTES (BM*BK*2)             // 8192
#define B_STG_BYTES (BN*BK*2)             // 8192
#define STAGE_BYTES (A_STG_BYTES + B_STG_BYTES)   // 16384
#define SMEM_TOTAL (STAGES * STAGE_BYTES)         // 65536

// fp16 staging buffers (device globals: allocation-free scratch)
__device__ __half g_Wh[(size_t)OUT_F * IN_F];   // 90 MB
__device__ __half g_Xh[(size_t)MROWS * IN_F];   // 67 MB

// ============================================================
// Dequant: W_q[32, NG] int32 byte codes -> g_Wh[OUT_F, IN_F] fp16
// ============================================================
__global__ void __launch_bounds__(256) dequant_kernel(const int* __restrict__ Wq,
                                                      const float* __restrict__ scale,
                                                      const float* __restrict__ zero) {
    int idx = blockIdx.x * 256 + threadIdx.x;   // 0 .. 32*(NG/4)-1
    const int G4 = NG / 4;                       // 176128
    int rr = idx / G4;                           // 0..31
    int g  = (idx - rr * G4) * 4;                // group base (mult of 4)
    int gb = g >> 12;                            // g / 4096
    int i  = g & 4095;

    int4   w  = *reinterpret_cast<const int4*>(Wq + (size_t)rr * NG + g);
    float4 s4 = *reinterpret_cast<const float4*>(scale + g);
    float4 z4 = *reinterpret_cast<const float4*>(zero + g);

    float hx = ((float)((w.x >> 4) & 0xF) - z4.x) * s4.x;
    float hy = ((float)((w.y >> 4) & 0xF) - z4.y) * s4.y;
    float hz = ((float)((w.z >> 4) & 0xF) - z4.z) * s4.z;
    float hw = ((float)((w.w >> 4) & 0xF) - z4.w) * s4.w;
    float lx = ((float)(w.x & 0xF) - z4.x) * s4.x;
    float ly = ((float)(w.y & 0xF) - z4.y) * s4.y;
    float lz = ((float)(w.z & 0xF) - z4.z) * s4.z;
    float lw = ((float)(w.w & 0xF) - z4.w) * s4.w;

    int o_hi = rr * 172 + gb;
    int o_lo = o_hi + 32 * 172;
    __half2* ph = reinterpret_cast<__half2*>(g_Wh + (size_t)o_hi * IN_F + i);
    __half2* pl = reinterpret_cast<__half2*>(g_Wh + (size_t)o_lo * IN_F + i);
    ph[0] = __floats2half2_rn(hx, hy);
    ph[1] = __floats2half2_rn(hz, hw);
    pl[0] = __floats2half2_rn(lx, ly);
    pl[1] = __floats2half2_rn(lz, lw);
}

// ============================================================
// x fp32 -> fp16
// ============================================================
__global__ void __launch_bounds__(256) convert_x_kernel(const float* __restrict__ x) {
    size_t base = ((size_t)blockIdx.x * 256 + threadIdx.x) * 8;
    float4 f0 = *reinterpret_cast<const float4*>(x + base);
    float4 f1 = *reinterpret_cast<const float4*>(x + base + 4);
    __half2 h0 = __floats2half2_rn(f0.x, f0.y);
    __half2 h1 = __floats2half2_rn(f0.z, f0.w);
    __half2 h2 = __floats2half2_rn(f1.x, f1.y);
    __half2 h3 = __floats2half2_rn(f1.z, f1.w);
    uint4 pack;
    pack.x = *reinterpret_cast<uint32_t*>(&h0);
    pack.y = *reinterpret_cast<uint32_t*>(&h1);
    pack.z = *reinterpret_cast<uint32_t*>(&h2);
    pack.w = *reinterpret_cast<uint32_t*>(&h3);
    *reinterpret_cast<uint4*>(g_Xh + base) = pack;
}

// ============================================================
// PTX helpers
// ============================================================
__device__ __forceinline__ uint32_t smem_u32(const void* p) {
    return (uint32_t)__cvta_generic_to_shared(p);
}
__device__ __forceinline__ void cp_async16(uint32_t dst, const void* src) {
    asm volatile("cp.async.cg.shared.global [%0], [%1], 16;" :: "r"(dst), "l"(src) : "memory");
}
__device__ __forceinline__ void cp_commit() {
    asm volatile("cp.async.commit_group;" ::: "memory");
}
template<int N>
__device__ __forceinline__ void cp_wait() {
    asm volatile("cp.async.wait_group %0;" :: "n"(N) : "memory");
}
__device__ __forceinline__ void ldsm_x4(uint32_t* r, uint32_t addr) {
    asm volatile("ldmatrix.sync.aligned.m8n8.x4.shared.b16 {%0,%1,%2,%3}, [%4];"
                 : "=r"(r[0]), "=r"(r[1]), "=r"(r[2]), "=r"(r[3]) : "r"(addr));
}
// fp16-accumulator MMA: D,C in 2 regs (4 halves)
__device__ __forceinline__ void mma16816_f16(uint32_t* c, const uint32_t* a, const uint32_t* b) {
    asm volatile(
        "mma.sync.aligned.m16n8k16.row.col.f16.f16.f16.f16 "
        "{%0,%1}, {%2,%3,%4,%5}, {%6,%7}, {%0,%1};"
        : "+r"(c[0]), "+r"(c[1])
        : "r"(a[0]), "r"(a[1]), "r"(a[2]), "r"(a[3]), "r"(b[0]), "r"(b[1]));
}

// ============================================================
// GEMM: out[m,n] = sum_k Xh[m,k]*Wh[n,k] + bias[n]
// BM=BN=128, BK=32, 4-stage cp.async, 4 warps (2x2), warp tile 64x64.
// 2 CTAs/SM. fp16-accumulator MMA chained over Kc=32 (one kb),
// promoted to fp32 accumulators every kb.
// smem: 64B rows, 16B chunk swizzle c -> c ^ ((row>>1)&3)
// ============================================================
__global__ void __launch_bounds__(128) gemm_kernel(const __half* __restrict__ X,
                                                   const __half* __restrict__ W,
                                                   const float* __restrict__ bias,
                                                   float* __restrict__ out) {
    extern __shared__ char smem[];
    const uint32_t sBase = smem_u32(smem);

    int tid = threadIdx.x;
    int wid = tid >> 5;
    int lane = tid & 31;
    int wm = wid >> 1;          // 0..1  (64-row slab)
    int wn = wid & 1;           // 0..1  (64-col slab)

    // supertile raster: 16 m-tiles per supercolumn
    const int NT = OUT_F / BN;  // 86
    const int GM = 16;
    const int per = GM * NT;    // 1376
    int sc  = blockIdx.x / per;           // 0..3
    int rem = blockIdx.x - sc * per;
    int n_tile = rem / GM;
    int m_tile = sc * GM + (rem - (rem / GM) * GM);

    const __half* gA = X + (size_t)(m_tile * BM) * IN_F;
    const __half* gB = W + (size_t)(n_tile * BN) * IN_F;

    // cp.async: each tile = 512 x 16B chunks, 128 threads -> 4 chunks/thread
    uint32_t stOff[4], glOff[4];
    #pragma unroll
    for (int j = 0; j < 4; j++) {
        int ci  = tid + j * 128;
        int row = ci >> 2, c = ci & 3;
        int sw  = (row >> 1) & 3;
        stOff[j] = row * 64 + ((c ^ sw) << 4);
        glOff[j] = row * IN_F + c * 8;
    }

    // ldmatrix offsets (k-step toggles via ^32)
    uint32_t aOff[4], bOff[4];
    #pragma unroll
    for (int mt = 0; mt < 4; mt++) {
        int row = wm * 64 + mt * 16 + (lane & 15);
        int c0  = lane >> 4;
        int sw  = (row >> 1) & 3;
        aOff[mt] = row * 64 + ((c0 ^ sw) << 4);
    }
    #pragma unroll
    for (int bt = 0; bt < 4; bt++) {
        int row = wn * 64 + bt * 16 + (lane & 7) + ((lane >> 4) << 3);
        int c0  = (lane >> 3) & 1;
        int sw  = (row >> 1) & 3;
        bOff[bt] = row * 64 + ((c0 ^ sw) << 4);
    }

    float acc[4][8][4];
    #pragma unroll
    for (int mt = 0; mt < 4; mt++)
        #pragma unroll
        for (int nt = 0; nt < 8; nt++)
            #pragma unroll
            for (int j = 0; j < 4; j++) acc[mt][nt][j] = 0.f;

    // prologue: stages 0..2
    #pragma unroll
    for (int kb = 0; kb < STAGES - 1; kb++) {
        uint32_t st = sBase + kb * STAGE_BYTES;
        #pragma unroll
        for (int j = 0; j < 4; j++) {
            cp_async16(st + stOff[j],               gA + kb * BK + glOff[j]);
            cp_async16(st + A_STG_BYTES + stOff[j], gB + kb * BK + glOff[j]);
        }
        cp_commit();
    }

    for (int kb = 0; kb < NKB; kb++) {
        int s = kb & (STAGES - 1);
        cp_wait<STAGES - 2>();
        __syncthreads();

        int kn = kb + STAGES - 1;
        if (kn < NKB) {
            uint32_t st = sBase + (kn & (STAGES - 1)) * STAGE_BYTES;
            #pragma unroll
            for (int j = 0; j < 4; j++) {
                cp_async16(st + stOff[j],               gA + kn * BK + glOff[j]);
                cp_async16(st + A_STG_BYTES + stOff[j], gB + kn * BK + glOff[j]);
            }
        }
        cp_commit();

        uint32_t stA = sBase + s * STAGE_BYTES;
        uint32_t stB = stA + A_STG_BYTES;

        // both k-steps' A fragments (32 regs)
        uint32_t a[2][4][4];
        #pragma unroll
        for (int ks = 0; ks < 2; ks++)
            #pragma unroll
            for (int mt = 0; mt < 4; mt++)
                ldsm_x4(a[ks][mt], stA + (aOff[mt] ^ (ks << 5)));

        #pragma unroll
        for (int bt = 0; bt < 4; bt++) {
            uint32_t b0[4], b1[4];           // ks=0 / ks=1 for this bt
            ldsm_x4(b0, stB + bOff[bt]);
            ldsm_x4(b1, stB + (bOff[bt] ^ 32));
            #pragma unroll
            for (int mt = 0; mt < 4; mt++) {
                #pragma unroll
                for (int nf = 0; nf < 2; nf++) {
                    uint32_t ch[2]; ch[0] = 0u; ch[1] = 0u;
                    mma16816_f16(ch, a[0][mt], b0 + 2 * nf);   // K 0..15
                    mma16816_f16(ch, a[1][mt], b1 + 2 * nf);   // K 16..31
                    float* ac = acc[mt][bt * 2 + nf];
                    float2 f0 = __half22float2(*reinterpret_cast<__half2*>(&ch[0]));
                    float2 f1 = __half22float2(*reinterpret_cast<__half2*>(&ch[1]));
                    ac[0] += f0.x; ac[1] += f0.y;
                    ac[2] += f1.x; ac[3] += f1.y;
                }
            }
        }
    }

    // epilogue: direct global writes + bias
    int m0 = m_tile * BM + wm * 64;
    int n0 = n_tile * BN + wn * 64;
    int rl = lane >> 2;
    int cl = (lane & 3) * 2;
    #pragma unroll
    for (int mt = 0; mt < 4; mt++) {
        #pragma unroll
        for (int nt = 0; nt < 8; nt++) {
            int col = n0 + nt * 8 + cl;
            float2 b2 = *reinterpret_cast<const float2*>(bias + col);
            size_t r0 = (size_t)(m0 + mt * 16 + rl) * OUT_F + col;
            size_t r1 = r0 + 8 * OUT_F;
            float2 v0 = { acc[mt][nt][0] + b2.x, acc[mt][nt][1] + b2.y };
            float2 v1 = { acc[mt][nt][2] + b2.x, acc[mt][nt][3] + b2.y };
            *reinterpret_cast<float2*>(out + r0) = v0;
            *reinterpret_cast<float2*>(out + r1) = v1;
        }
    }
}

// ============================================================
// Host launch
// ============================================================
extern "C" void kernel_launch(void* const* d_in, const int* in_sizes, int n_in,
                              void* d_out, int out_size) {
    const float* x     = (const float*)d_in[0];
    const int*   Wq    = (const int*)d_in[1];
    const float* scale = (const float*)d_in[2];
    const float* zero  = (const float*)d_in[3];
    const float* bias  = (const float*)d_in[4];
    float* out = (float*)d_out;

    void *wh = nullptr, *xh = nullptr;
    cudaGetSymbolAddress(&wh, g_Wh);
    cudaGetSymbolAddress(&xh, g_Xh);

    dequant_kernel<<<(32 * (NG / 4)) / 256, 256>>>(Wq, scale, zero);
    convert_x_kernel<<<(MROWS * IN_F) / (256 * 8), 256>>>(x);

    cudaFuncSetAttribute(gemm_kernel, cudaFuncAttributeMaxDynamicSharedMemorySize, SMEM_TOTAL);
    int grid = (MROWS / BM) * (OUT_F / BN);   // 64 * 86 = 5504
    gemm_kernel<<<grid, 128, SMEM_TOTAL>>>((const __half*)xh, (const __half*)wh, bias, out);
}

// round 15
// speedup vs baseline: 1.4395x; 1.4395x over previous
#include <cuda_runtime.h>
#include <cuda_fp16.h>
#include <cstdint>

#define IN_F   4096
#define OUT_F  11008
#define NG     704512          // IN_F*OUT_F/64
#define MROWS  8192            // 4*2048

#define BM 128
#define BN 128
#define BK 32
#define NKB (IN_F / BK)        // 128
#define STAGES 4
#define A_STG_BYTES (BM*BK*2)             // 8192
#define B_STG_BYTES (BN*BK*2)             // 8192
#define STAGE_BYTES (A_STG_BYTES + B_STG_BYTES)   // 16384
#define SMEM_TOTAL (STAGES * STAGE_BYTES)         // 65536

// prep grid split
#define DQ_BLOCKS ((32 * (NG / 4)) / 256)           // 22016
#define CV_BLOCKS ((MROWS * IN_F) / (256 * 8))      // 16384
#define PREP_BLOCKS (DQ_BLOCKS + CV_BLOCKS)

// fp16 staging buffers (device globals: allocation-free scratch)
__device__ __half g_Wh[(size_t)OUT_F * IN_F];   // 90 MB
__device__ __half g_Xh[(size_t)MROWS * IN_F];   // 67 MB

// ============================================================
// Fused prep: blocks [0, DQ_BLOCKS) dequantize W, the rest convert x.
// Both halves are independent and DRAM-bound; fusing them fills the
// memory system once instead of two sequential ramps.
// ============================================================
__global__ void __launch_bounds__(256) prep_kernel(const int* __restrict__ Wq,
                                                   const float* __restrict__ scale,
                                                   const float* __restrict__ zero,
                                                   const float* __restrict__ x) {
    if (blockIdx.x < DQ_BLOCKS) {
        // ---- dequant: W_q[32, NG] byte codes -> g_Wh[OUT_F, IN_F] fp16 ----
        int idx = blockIdx.x * 256 + threadIdx.x;   // 0 .. 32*(NG/4)-1
        const int G4 = NG / 4;                       // 176128
        int rr = idx / G4;                           // 0..31
        int g  = (idx - rr * G4) * 4;                // group base (mult of 4)
        int gb = g >> 12;                            // g / 4096
        int i  = g & 4095;

        int4   w  = *reinterpret_cast<const int4*>(Wq + (size_t)rr * NG + g);
        float4 s4 = *reinterpret_cast<const float4*>(scale + g);
        float4 z4 = *reinterpret_cast<const float4*>(zero + g);

        float hx = ((float)((w.x >> 4) & 0xF) - z4.x) * s4.x;
        float hy = ((float)((w.y >> 4) & 0xF) - z4.y) * s4.y;
        float hz = ((float)((w.z >> 4) & 0xF) - z4.z) * s4.z;
        float hw = ((float)((w.w >> 4) & 0xF) - z4.w) * s4.w;
        float lx = ((float)(w.x & 0xF) - z4.x) * s4.x;
        float ly = ((float)(w.y & 0xF) - z4.y) * s4.y;
        float lz = ((float)(w.z & 0xF) - z4.z) * s4.z;
        float lw = ((float)(w.w & 0xF) - z4.w) * s4.w;

        int o_hi = rr * 172 + gb;
        int o_lo = o_hi + 32 * 172;
        __half2* ph = reinterpret_cast<__half2*>(g_Wh + (size_t)o_hi * IN_F + i);
        __half2* pl = reinterpret_cast<__half2*>(g_Wh + (size_t)o_lo * IN_F + i);
        ph[0] = __floats2half2_rn(hx, hy);
        ph[1] = __floats2half2_rn(hz, hw);
        pl[0] = __floats2half2_rn(lx, ly);
        pl[1] = __floats2half2_rn(lz, lw);
    } else {
        // ---- convert: x fp32 -> g_Xh fp16 ----
        size_t base = ((size_t)(blockIdx.x - DQ_BLOCKS) * 256 + threadIdx.x) * 8;
        float4 f0 = *reinterpret_cast<const float4*>(x + base);
        float4 f1 = *reinterpret_cast<const float4*>(x + base + 4);
        __half2 h0 = __floats2half2_rn(f0.x, f0.y);
        __half2 h1 = __floats2half2_rn(f0.z, f0.w);
        __half2 h2 = __floats2half2_rn(f1.x, f1.y);
        __half2 h3 = __floats2half2_rn(f1.z, f1.w);
        uint4 pack;
        pack.x = *reinterpret_cast<uint32_t*>(&h0);
        pack.y = *reinterpret_cast<uint32_t*>(&h1);
        pack.z = *reinterpret_cast<uint32_t*>(&h2);
        pack.w = *reinterpret_cast<uint32_t*>(&h3);
        *reinterpret_cast<uint4*>(g_Xh + base) = pack;
    }
}

// ============================================================
// PTX helpers
// ============================================================
__device__ __forceinline__ uint32_t smem_u32(const void* p) {
    return (uint32_t)__cvta_generic_to_shared(p);
}
__device__ __forceinline__ void cp_async16(uint32_t dst, const void* src) {
    asm volatile("cp.async.cg.shared.global [%0], [%1], 16;" :: "r"(dst), "l"(src) : "memory");
}
__device__ __forceinline__ void cp_commit() {
    asm volatile("cp.async.commit_group;" ::: "memory");
}
template<int N>
__device__ __forceinline__ void cp_wait() {
    asm volatile("cp.async.wait_group %0;" :: "n"(N) : "memory");
}
__device__ __forceinline__ void ldsm_x4(uint32_t* r, uint32_t addr) {
    asm volatile("ldmatrix.sync.aligned.m8n8.x4.shared.b16 {%0,%1,%2,%3}, [%4];"
                 : "=r"(r[0]), "=r"(r[1]), "=r"(r[2]), "=r"(r[3]) : "r"(addr));
}
__device__ __forceinline__ void mma16816(float* c, const uint32_t* a, const uint32_t* b) {
    asm volatile(
        "mma.sync.aligned.m16n8k16.row.col.f32.f16.f16.f32 "
        "{%0,%1,%2,%3}, {%4,%5,%6,%7}, {%8,%9}, {%0,%1,%2,%3};"
        : "+f"(c[0]), "+f"(c[1]), "+f"(c[2]), "+f"(c[3])
        : "r"(a[0]), "r"(a[1]), "r"(a[2]), "r"(a[3]), "r"(b[0]), "r"(b[1]));
}

// ============================================================
// GEMM: out[m,n] = sum_k Xh[m,k]*Wh[n,k] + bias[n]
// BM=BN=128, BK=32, 4-stage cp.async, 4 warps (2x2), warp tile 64x64
// 2 CTAs/SM. smem: 64B rows, 16B chunk swizzle c -> c ^ ((row>>1)&3)
// (champion mainloop — byte-identical to the 1732.8us measurement)
// ============================================================
__global__ void __launch_bounds__(128) gemm_kernel(const __half* __restrict__ X,
                                                   const __half* __restrict__ W,
                                                   const float* __restrict__ bias,
                                                   float* __restrict__ out) {
    extern __shared__ char smem[];
    const uint32_t sBase = smem_u32(smem);

    int tid = threadIdx.x;
    int wid = tid >> 5;
    int lane = tid & 31;
    int wm = wid >> 1;          // 0..1  (64-row slab)
    int wn = wid & 1;           // 0..1  (64-col slab)

    // supertile raster: 16 m-tiles per supercolumn
    const int NT = OUT_F / BN;  // 86
    const int GM = 16;
    const int per = GM * NT;    // 1376
    int sc  = blockIdx.x / per;           // 0..3
    int rem = blockIdx.x - sc * per;
    int n_tile = rem / GM;
    int m_tile = sc * GM + (rem - (rem / GM) * GM);

    const __half* gA = X + (size_t)(m_tile * BM) * IN_F;
    const __half* gB = W + (size_t)(n_tile * BN) * IN_F;

    // cp.async: each tile = 512 x 16B chunks, 128 threads -> 4 chunks/thread
    uint32_t stOff[4], glOff[4];
    #pragma unroll
    for (int j = 0; j < 4; j++) {
        int ci  = tid + j * 128;
        int row = ci >> 2, c = ci & 3;
        int sw  = (row >> 1) & 3;
        stOff[j] = row * 64 + ((c ^ sw) << 4);
        glOff[j] = row * IN_F + c * 8;
    }

    // ldmatrix offsets (k-step toggles via ^32)
    uint32_t aOff[4], bOff[4];
    #pragma unroll
    for (int mt = 0; mt < 4; mt++) {
        int row = wm * 64 + mt * 16 + (lane & 15);
        int c0  = lane >> 4;
        int sw  = (row >> 1) & 3;
        aOff[mt] = row * 64 + ((c0 ^ sw) << 4);
    }
    #pragma unroll
    for (int bt = 0; bt < 4; bt++) {
        int row = wn * 64 + bt * 16 + (lane & 7) + ((lane >> 4) << 3);
        int c0  = (lane >> 3) & 1;
        int sw  = (row >> 1) & 3;
        bOff[bt] = row * 64 + ((c0 ^ sw) << 4);
    }

    float acc[4][8][4];
    #pragma unroll
    for (int mt = 0; mt < 4; mt++)
        #pragma unroll
        for (int nt = 0; nt < 8; nt++)
            #pragma unroll
            for (int j = 0; j < 4; j++) acc[mt][nt][j] = 0.f;

    // prologue: stages 0..2
    #pragma unroll
    for (int kb = 0; kb < STAGES - 1; kb++) {
        uint32_t st = sBase + kb * STAGE_BYTES;
        #pragma unroll
        for (int j = 0; j < 4; j++) {
            cp_async16(st + stOff[j],               gA + kb * BK + glOff[j]);
            cp_async16(st + A_STG_BYTES + stOff[j], gB + kb * BK + glOff[j]);
        }
        cp_commit();
    }

    for (int kb = 0; kb < NKB; kb++) {
        int s = kb & (STAGES - 1);
        cp_wait<STAGES - 2>();
        __syncthreads();

        int kn = kb + STAGES - 1;
        if (kn < NKB) {
            uint32_t st = sBase + (kn & (STAGES - 1)) * STAGE_BYTES;
            #pragma unroll
            for (int j = 0; j < 4; j++) {
                cp_async16(st + stOff[j],               gA + kn * BK + glOff[j]);
                cp_async16(st + A_STG_BYTES + stOff[j], gB + kn * BK + glOff[j]);
            }
        }
        cp_commit();

        uint32_t stA = sBase + s * STAGE_BYTES;
        uint32_t stB = stA + A_STG_BYTES;
        #pragma unroll
        for (int ks = 0; ks < 2; ks++) {
            uint32_t kx = ks << 5;
            uint32_t a[4][4];
            #pragma unroll
            for (int mt = 0; mt < 4; mt++)
                ldsm_x4(a[mt], stA + (aOff[mt] ^ kx));
            // B window: one ldsm.x4 (= 2 n-frags) live at a time, 8 MMAs each
            #pragma unroll
            for (int bt = 0; bt < 4; bt++) {
                uint32_t r[4];
                ldsm_x4(r, stB + (bOff[bt] ^ kx));
                #pragma unroll
                for (int mt = 0; mt < 4; mt++) {
                    mma16816(acc[mt][bt * 2 + 0], a[mt], r + 0);
                    mma16816(acc[mt][bt * 2 + 1], a[mt], r + 2);
                }
            }
        }
    }

    // epilogue: direct global writes + bias
    int m0 = m_tile * BM + wm * 64;
    int n0 = n_tile * BN + wn * 64;
    int rl = lane >> 2;
    int cl = (lane & 3) * 2;
    #pragma unroll
    for (int mt = 0; mt < 4; mt++) {
        #pragma unroll
        for (int nt = 0; nt < 8; nt++) {
            int col = n0 + nt * 8 + cl;
            float2 b2 = *reinterpret_cast<const float2*>(bias + col);
            size_t r0 = (size_t)(m0 + mt * 16 + rl) * OUT_F + col;
            size_t r1 = r0 + 8 * OUT_F;
            float2 v0 = { acc[mt][nt][0] + b2.x, acc[mt][nt][1] + b2.y };
            float2 v1 = { acc[mt][nt][2] + b2.x, acc[mt][nt][3] + b2.y };
            *reinterpret_cast<float2*>(out + r0) = v0;
            *reinterpret_cast<float2*>(out + r1) = v1;
        }
    }
}

// ============================================================
// Host launch
// ============================================================
extern "C" void kernel_launch(void* const* d_in, const int* in_sizes, int n_in,
                              void* d_out, int out_size) {
    const float* x     = (const float*)d_in[0];
    const int*   Wq    = (const int*)d_in[1];
    const float* scale = (const float*)d_in[2];
    const float* zero  = (const float*)d_in[3];
    const float* bias  = (const float*)d_in[4];
    float* out = (float*)d_out;

    void *wh = nullptr, *xh = nullptr;
    cudaGetSymbolAddress(&wh, g_Wh);
    cudaGetSymbolAddress(&xh, g_Xh);

    prep_kernel<<<PREP_BLOCKS, 256>>>(Wq, scale, zero, x);

    cudaFuncSetAttribute(gemm_kernel, cudaFuncAttributeMaxDynamicSharedMemorySize, SMEM_TOTAL);
    int grid = (MROWS / BM) * (OUT_F / BN);   // 64 * 86 = 5504
    gemm_kernel<<<grid, 128, SMEM_TOTAL>>>((const __half*)xh, (const __half*)wh, bias, out);
}